// round 2
// baseline (speedup 1.0000x reference)
#include <cuda_runtime.h>

#define NN 100000
#define EE 1600000

// ---- scratch (device globals: allocation-free) ----
__device__ int   g_deg[NN];
__device__ int   g_off[NN + 1];
__device__ int   g_cur[NN];
__device__ int   g_csr[EE];
__device__ float g_mean1[(size_t)NN * 64];
__device__ float g_h[(size_t)NN * 128];
__device__ float g_mean2[(size_t)NN * 128];

// ---------------- CSR build ----------------
__global__ void zero_deg_kernel(int n) {
    int i = blockIdx.x * blockDim.x + threadIdx.x;
    if (i < n) g_deg[i] = 0;
}

__global__ void hist_kernel(const int* __restrict__ ei, int E) {
    int e = blockIdx.x * blockDim.x + threadIdx.x;
    if (e < E) atomicAdd(&g_deg[ei[E + e]], 1);
}

__global__ void scan_kernel(int N) {
    __shared__ int ssum[1024];
    int t = threadIdx.x;
    int chunk = (N + 1023) / 1024;
    int lo = t * chunk;
    int hi = min(N, lo + chunk);
    int s = 0;
    for (int i = lo; i < hi; ++i) s += g_deg[i];
    ssum[t] = s;
    __syncthreads();
    for (int d = 1; d < 1024; d <<= 1) {
        int v = (t >= d) ? ssum[t - d] : 0;
        __syncthreads();
        ssum[t] += v;
        __syncthreads();
    }
    int run = ssum[t] - s;  // exclusive prefix of this thread's chunk
    for (int i = lo; i < hi; ++i) {
        g_off[i] = run;
        g_cur[i] = run;
        run += g_deg[i];
    }
    if (t == 1023) g_off[N] = ssum[1023];
}

__global__ void scatter_kernel(const int* __restrict__ ei, int E) {
    int e = blockIdx.x * blockDim.x + threadIdx.x;
    if (e < E) {
        int d = ei[E + e];
        int p = atomicAdd(&g_cur[d], 1);
        g_csr[p] = ei[e];
    }
}

// ---------------- aggregation (warp per dst node) ----------------
__global__ void agg64_kernel(const float* __restrict__ x, float* __restrict__ mean, int N) {
    int gw = (blockIdx.x * blockDim.x + threadIdx.x) >> 5;
    int lane = threadIdx.x & 31;
    if (gw >= N) return;
    int s = g_off[gw], e = g_off[gw + 1];
    float ax = 0.f, ay = 0.f;
    int j = s;
    for (; j + 4 <= e; j += 4) {
        int u0 = g_csr[j], u1 = g_csr[j + 1], u2 = g_csr[j + 2], u3 = g_csr[j + 3];
        float2 v0 = *(const float2*)(x + (size_t)u0 * 64 + lane * 2);
        float2 v1 = *(const float2*)(x + (size_t)u1 * 64 + lane * 2);
        float2 v2 = *(const float2*)(x + (size_t)u2 * 64 + lane * 2);
        float2 v3 = *(const float2*)(x + (size_t)u3 * 64 + lane * 2);
        ax += v0.x + v1.x + v2.x + v3.x;
        ay += v0.y + v1.y + v2.y + v3.y;
    }
    for (; j < e; ++j) {
        int u = g_csr[j];
        float2 v = *(const float2*)(x + (size_t)u * 64 + lane * 2);
        ax += v.x; ay += v.y;
    }
    float inv = 1.f / (float)max(e - s, 1);
    float2 o; o.x = ax * inv; o.y = ay * inv;
    *(float2*)(mean + (size_t)gw * 64 + lane * 2) = o;
}

__global__ void agg128_kernel(const float* __restrict__ x, float* __restrict__ mean, int N) {
    int gw = (blockIdx.x * blockDim.x + threadIdx.x) >> 5;
    int lane = threadIdx.x & 31;
    if (gw >= N) return;
    int s = g_off[gw], e = g_off[gw + 1];
    float a0 = 0.f, a1 = 0.f, a2 = 0.f, a3 = 0.f;
    int j = s;
    for (; j + 4 <= e; j += 4) {
        int u0 = g_csr[j], u1 = g_csr[j + 1], u2 = g_csr[j + 2], u3 = g_csr[j + 3];
        float4 v0 = *(const float4*)(x + (size_t)u0 * 128 + lane * 4);
        float4 v1 = *(const float4*)(x + (size_t)u1 * 128 + lane * 4);
        float4 v2 = *(const float4*)(x + (size_t)u2 * 128 + lane * 4);
        float4 v3 = *(const float4*)(x + (size_t)u3 * 128 + lane * 4);
        a0 += v0.x + v1.x + v2.x + v3.x;
        a1 += v0.y + v1.y + v2.y + v3.y;
        a2 += v0.z + v1.z + v2.z + v3.z;
        a3 += v0.w + v1.w + v2.w + v3.w;
    }
    for (; j < e; ++j) {
        int u = g_csr[j];
        float4 v = *(const float4*)(x + (size_t)u * 128 + lane * 4);
        a0 += v.x; a1 += v.y; a2 += v.z; a3 += v.w;
    }
    float inv = 1.f / (float)max(e - s, 1);
    float4 o; o.x = a0 * inv; o.y = a1 * inv; o.z = a2 * inv; o.w = a3 * inv;
    *(float4*)(mean + (size_t)gw * 128 + lane * 4) = o;
}

// ---------------- fused dual-A GEMM: out = A1*Wl^T + A2*Wr^T + bl (opt relu) ----------------
// Tile: 64 nodes x 128 H per block, 256 threads, K-chunks of 16.
// Thread t: lane = t&31 handles h in {lane, lane+32, lane+64, lane+96};
//           warp  = t>>5 handles nodes n0 + warp*8 .. +7.  acc[8][4].
template <int K, bool RELU>
__global__ void combine_kernel(const float* __restrict__ A1,
                               const float* __restrict__ A2,
                               const float* __restrict__ Wl,
                               const float* __restrict__ bl,
                               const float* __restrict__ Wr,
                               float* __restrict__ out, int N) {
    constexpr int KC = 16;
    __shared__ float sA1[KC][65];       // [k][n], pad 65: conflict-free stores, broadcast reads
    __shared__ float sA2[KC][65];
    __shared__ float sWl[128][KC + 1];  // [h][k], pad 17: conflict-free reads (lane stride 17)
    __shared__ float sWr[128][KC + 1];

    int tid = threadIdx.x;
    int lane = tid & 31;
    int w = tid >> 5;
    int n0 = blockIdx.x * 64;

    float acc[8][4];
#pragma unroll
    for (int i = 0; i < 8; ++i)
#pragma unroll
        for (int j = 0; j < 4; ++j) acc[i][j] = 0.f;

    for (int k0 = 0; k0 < K; k0 += KC) {
        // A tiles: 64 rows x 16 k = 256 float4 per array, 1 per thread
        {
            int n = tid >> 2;      // 0..63
            int k4 = tid & 3;      // 0..3
            float4 v1 = make_float4(0.f, 0.f, 0.f, 0.f);
            float4 v2 = v1;
            if (n0 + n < N) {
                v1 = *(const float4*)(A1 + (size_t)(n0 + n) * K + k0 + k4 * 4);
                v2 = *(const float4*)(A2 + (size_t)(n0 + n) * K + k0 + k4 * 4);
            }
            sA1[k4 * 4 + 0][n] = v1.x; sA1[k4 * 4 + 1][n] = v1.y;
            sA1[k4 * 4 + 2][n] = v1.z; sA1[k4 * 4 + 3][n] = v1.w;
            sA2[k4 * 4 + 0][n] = v2.x; sA2[k4 * 4 + 1][n] = v2.y;
            sA2[k4 * 4 + 2][n] = v2.z; sA2[k4 * 4 + 3][n] = v2.w;
        }
        // W tiles: 128 rows x 16 k = 512 float4 per array, 2 per thread
#pragma unroll
        for (int it = 0; it < 2; ++it) {
            int item = tid + it * 256;
            int h = item >> 2;     // 0..127
            int k4 = item & 3;
            float4 vl = *(const float4*)(Wl + (size_t)h * K + k0 + k4 * 4);
            float4 vr = *(const float4*)(Wr + (size_t)h * K + k0 + k4 * 4);
            sWl[h][k4 * 4 + 0] = vl.x; sWl[h][k4 * 4 + 1] = vl.y;
            sWl[h][k4 * 4 + 2] = vl.z; sWl[h][k4 * 4 + 3] = vl.w;
            sWr[h][k4 * 4 + 0] = vr.x; sWr[h][k4 * 4 + 1] = vr.y;
            sWr[h][k4 * 4 + 2] = vr.z; sWr[h][k4 * 4 + 3] = vr.w;
        }
        __syncthreads();
#pragma unroll
        for (int kk = 0; kk < KC; ++kk) {
            float wl[4], wr[4];
#pragma unroll
            for (int j = 0; j < 4; ++j) {
                wl[j] = sWl[lane + 32 * j][kk];
                wr[j] = sWr[lane + 32 * j][kk];
            }
#pragma unroll
            for (int i = 0; i < 8; ++i) {
                float a1 = sA1[kk][w * 8 + i];
                float a2 = sA2[kk][w * 8 + i];
#pragma unroll
                for (int j = 0; j < 4; ++j)
                    acc[i][j] += a1 * wl[j] + a2 * wr[j];
            }
        }
        __syncthreads();
    }

    float b[4];
#pragma unroll
    for (int j = 0; j < 4; ++j) b[j] = bl[lane + 32 * j];

#pragma unroll
    for (int i = 0; i < 8; ++i) {
        int n = n0 + w * 8 + i;
        if (n < N) {
#pragma unroll
            for (int j = 0; j < 4; ++j) {
                float v = acc[i][j] + b[j];
                if (RELU) v = fmaxf(v, 0.f);
                out[(size_t)n * 128 + lane + 32 * j] = v;
            }
        }
    }
}

// ---------------- launch ----------------
extern "C" void kernel_launch(void* const* d_in, const int* in_sizes, int n_in,
                              void* d_out, int out_size) {
    const float* x   = (const float*)d_in[0];
    const int*   ei  = (const int*)d_in[1];
    const float* Wl1 = (const float*)d_in[2];
    const float* bl1 = (const float*)d_in[3];
    const float* Wr1 = (const float*)d_in[4];
    const float* Wl2 = (const float*)d_in[5];
    const float* bl2 = (const float*)d_in[6];
    const float* Wr2 = (const float*)d_in[7];
    float* out = (float*)d_out;

    int N = in_sizes[0] / 64;
    int E = in_sizes[1] / 2;

    void* p;
    cudaGetSymbolAddress(&p, g_mean1); float* mean1 = (float*)p;
    cudaGetSymbolAddress(&p, g_h);     float* hbuf  = (float*)p;
    cudaGetSymbolAddress(&p, g_mean2); float* mean2 = (float*)p;

    // CSR build
    zero_deg_kernel<<<(N + 255) / 256, 256>>>(N);
    hist_kernel<<<(E + 255) / 256, 256>>>(ei, E);
    scan_kernel<<<1, 1024>>>(N);
    scatter_kernel<<<(E + 255) / 256, 256>>>(ei, E);

    // Layer 1
    agg64_kernel<<<(N + 7) / 8, 256>>>(x, mean1, N);
    combine_kernel<64, true><<<(N + 63) / 64, 256>>>(mean1, x, Wl1, bl1, Wr1, hbuf, N);

    // Layer 2
    agg128_kernel<<<(N + 7) / 8, 256>>>(hbuf, mean2, N);
    combine_kernel<128, false><<<(N + 63) / 64, 256>>>(mean2, hbuf, Wl2, bl2, Wr2, out, N);
}

// round 9
// speedup vs baseline: 1.0690x; 1.0690x over previous
#include <cuda_runtime.h>

#define NN 100000
#define EE 1600000

typedef unsigned long long ull;

// ---- scratch (device globals: allocation-free) ----
__device__ int   g_deg[NN];
__device__ int   g_off[NN + 1];
__device__ int   g_cur[NN];
__device__ int   g_csr[EE];
__device__ float g_mean1[(size_t)NN * 64];
__device__ float g_h[(size_t)NN * 128];
__device__ float g_mean2[(size_t)NN * 128];

// packed f32x2 FMA: d = a*b + c per 32-bit lane (Blackwell packed-fp32 pipe)
__device__ __forceinline__ ull ffma2(ull a, ull b, ull c) {
    ull d;
    asm("fma.rn.f32x2 %0, %1, %2, %3;" : "=l"(d) : "l"(a), "l"(b), "l"(c));
    return d;
}
__device__ __forceinline__ ull dup2(float v) {
    unsigned u = __float_as_uint(v);
    return ((ull)u << 32) | u;
}

// ---------------- CSR build ----------------
__global__ void zero_deg_kernel(int n) {
    int i = blockIdx.x * blockDim.x + threadIdx.x;
    if (i < n) g_deg[i] = 0;
}

__global__ void hist_kernel(const int* __restrict__ ei, int E) {
    int e4 = (blockIdx.x * blockDim.x + threadIdx.x) * 4;
    if (e4 + 3 < E) {
        int4 d = *(const int4*)(ei + E + e4);
        atomicAdd(&g_deg[d.x], 1);
        atomicAdd(&g_deg[d.y], 1);
        atomicAdd(&g_deg[d.z], 1);
        atomicAdd(&g_deg[d.w], 1);
    } else {
        for (int e = e4; e < E; ++e) atomicAdd(&g_deg[ei[E + e]], 1);
    }
}

__global__ void scan_kernel(int N) {
    __shared__ int ssum[1024];
    int t = threadIdx.x;
    int chunk = (N + 1023) / 1024;
    int lo = t * chunk;
    int hi = min(N, lo + chunk);
    int s = 0;
    for (int i = lo; i < hi; ++i) s += g_deg[i];
    ssum[t] = s;
    __syncthreads();
    for (int d = 1; d < 1024; d <<= 1) {
        int v = (t >= d) ? ssum[t - d] : 0;
        __syncthreads();
        ssum[t] += v;
        __syncthreads();
    }
    int run = ssum[t] - s;  // exclusive prefix of this thread's chunk
    for (int i = lo; i < hi; ++i) {
        g_off[i] = run;
        g_cur[i] = run;
        run += g_deg[i];
    }
    if (t == 1023) g_off[N] = ssum[1023];
}

__global__ void scatter_kernel(const int* __restrict__ ei, int E) {
    int e4 = (blockIdx.x * blockDim.x + threadIdx.x) * 4;
    if (e4 + 3 < E) {
        int4 s = *(const int4*)(ei + e4);
        int4 d = *(const int4*)(ei + E + e4);
        int p0 = atomicAdd(&g_cur[d.x], 1);
        int p1 = atomicAdd(&g_cur[d.y], 1);
        int p2 = atomicAdd(&g_cur[d.z], 1);
        int p3 = atomicAdd(&g_cur[d.w], 1);
        g_csr[p0] = s.x;
        g_csr[p1] = s.y;
        g_csr[p2] = s.z;
        g_csr[p3] = s.w;
    } else {
        for (int e = e4; e < E; ++e) {
            int p = atomicAdd(&g_cur[ei[E + e]], 1);
            g_csr[p] = ei[e];
        }
    }
}

// ---------------- aggregation (warp per dst node) ----------------
__global__ void agg64_kernel(const float* __restrict__ x, float* __restrict__ mean, int N) {
    int gw = (blockIdx.x * blockDim.x + threadIdx.x) >> 5;
    int lane = threadIdx.x & 31;
    if (gw >= N) return;
    int s = g_off[gw], e = g_off[gw + 1];
    float ax = 0.f, ay = 0.f;
    int j = s;
    for (; j + 4 <= e; j += 4) {
        int u0 = g_csr[j], u1 = g_csr[j + 1], u2 = g_csr[j + 2], u3 = g_csr[j + 3];
        float2 v0 = *(const float2*)(x + (size_t)u0 * 64 + lane * 2);
        float2 v1 = *(const float2*)(x + (size_t)u1 * 64 + lane * 2);
        float2 v2 = *(const float2*)(x + (size_t)u2 * 64 + lane * 2);
        float2 v3 = *(const float2*)(x + (size_t)u3 * 64 + lane * 2);
        ax += v0.x + v1.x + v2.x + v3.x;
        ay += v0.y + v1.y + v2.y + v3.y;
    }
    for (; j < e; ++j) {
        int u = g_csr[j];
        float2 v = *(const float2*)(x + (size_t)u * 64 + lane * 2);
        ax += v.x; ay += v.y;
    }
    float inv = 1.f / (float)max(e - s, 1);
    float2 o; o.x = ax * inv; o.y = ay * inv;
    *(float2*)(mean + (size_t)gw * 64 + lane * 2) = o;
}

__global__ void agg128_kernel(const float* __restrict__ x, float* __restrict__ mean, int N) {
    int gw = (blockIdx.x * blockDim.x + threadIdx.x) >> 5;
    int lane = threadIdx.x & 31;
    if (gw >= N) return;
    int s = g_off[gw], e = g_off[gw + 1];
    float a0 = 0.f, a1 = 0.f, a2 = 0.f, a3 = 0.f;
    int j = s;
    for (; j + 4 <= e; j += 4) {
        int u0 = g_csr[j], u1 = g_csr[j + 1], u2 = g_csr[j + 2], u3 = g_csr[j + 3];
        float4 v0 = *(const float4*)(x + (size_t)u0 * 128 + lane * 4);
        float4 v1 = *(const float4*)(x + (size_t)u1 * 128 + lane * 4);
        float4 v2 = *(const float4*)(x + (size_t)u2 * 128 + lane * 4);
        float4 v3 = *(const float4*)(x + (size_t)u3 * 128 + lane * 4);
        a0 += v0.x + v1.x + v2.x + v3.x;
        a1 += v0.y + v1.y + v2.y + v3.y;
        a2 += v0.z + v1.z + v2.z + v3.z;
        a3 += v0.w + v1.w + v2.w + v3.w;
    }
    for (; j < e; ++j) {
        int u = g_csr[j];
        float4 v = *(const float4*)(x + (size_t)u * 128 + lane * 4);
        a0 += v.x; a1 += v.y; a2 += v.z; a3 += v.w;
    }
    float inv = 1.f / (float)max(e - s, 1);
    float4 o; o.x = a0 * inv; o.y = a1 * inv; o.z = a2 * inv; o.w = a3 * inv;
    *(float4*)(mean + (size_t)gw * 128 + lane * 4) = o;
}

// ---------------- fused dual-A GEMM via packed f32x2 ----------------
// out = A1*Wl^T + A2*Wr^T + bl (opt relu)
// Tile: 64 nodes x 128 H per block, 256 threads, K-chunks of 16.
// Node dim packed into f32x2 pairs: thread (w,lane) owns node pairs
// (w*8+2p, w*8+2p+1), p=0..3, and h columns lane+32j, j=0..3.
// W held in shared pre-duplicated as (w,w) 64-bit pairs -> inner loop is
// pure LDS.64 + FFMA2 (no per-iteration packing).
template <int K, bool RELU>
__global__ void combine_kernel(const float* __restrict__ A1,
                               const float* __restrict__ A2,
                               const float* __restrict__ Wl,
                               const float* __restrict__ bl,
                               const float* __restrict__ Wr,
                               float* __restrict__ out, int N) {
    constexpr int KC = 16;
    __shared__ float sA1[KC][66];        // [k][n], stride 66: 8B-aligned rows, conflict-free
    __shared__ float sA2[KC][66];
    __shared__ ull   sWl2[128][KC + 1];  // [h][k] duplicated pairs, odd ull stride
    __shared__ ull   sWr2[128][KC + 1];

    int tid = threadIdx.x;
    int lane = tid & 31;
    int w = tid >> 5;
    int n0 = blockIdx.x * 64;

    ull acc[4][4];
#pragma unroll
    for (int p = 0; p < 4; ++p)
#pragma unroll
        for (int j = 0; j < 4; ++j) acc[p][j] = 0ull;

    for (int k0 = 0; k0 < K; k0 += KC) {
        // A tiles: 64 rows x 16 k = 256 float4 per array, 1 per thread
        {
            int n = tid >> 2;      // 0..63
            int k4 = tid & 3;      // 0..3
            float4 v1 = make_float4(0.f, 0.f, 0.f, 0.f);
            float4 v2 = v1;
            if (n0 + n < N) {
                v1 = *(const float4*)(A1 + (size_t)(n0 + n) * K + k0 + k4 * 4);
                v2 = *(const float4*)(A2 + (size_t)(n0 + n) * K + k0 + k4 * 4);
            }
            sA1[k4 * 4 + 0][n] = v1.x; sA1[k4 * 4 + 1][n] = v1.y;
            sA1[k4 * 4 + 2][n] = v1.z; sA1[k4 * 4 + 3][n] = v1.w;
            sA2[k4 * 4 + 0][n] = v2.x; sA2[k4 * 4 + 1][n] = v2.y;
            sA2[k4 * 4 + 2][n] = v2.z; sA2[k4 * 4 + 3][n] = v2.w;
        }
        // W tiles: 128 h x 16 k = 512 float4 per array, 2 per thread; store duplicated
#pragma unroll
        for (int it = 0; it < 2; ++it) {
            int item = tid + it * 256;
            int h = item >> 2;     // 0..127
            int k4 = item & 3;
            float4 vl = *(const float4*)(Wl + (size_t)h * K + k0 + k4 * 4);
            float4 vr = *(const float4*)(Wr + (size_t)h * K + k0 + k4 * 4);
            sWl2[h][k4 * 4 + 0] = dup2(vl.x); sWl2[h][k4 * 4 + 1] = dup2(vl.y);
            sWl2[h][k4 * 4 + 2] = dup2(vl.z); sWl2[h][k4 * 4 + 3] = dup2(vl.w);
            sWr2[h][k4 * 4 + 0] = dup2(vr.x); sWr2[h][k4 * 4 + 1] = dup2(vr.y);
            sWr2[h][k4 * 4 + 2] = dup2(vr.z); sWr2[h][k4 * 4 + 3] = dup2(vr.w);
        }
        __syncthreads();
#pragma unroll
        for (int kk = 0; kk < KC; ++kk) {
            ull wl[4], wr[4];
#pragma unroll
            for (int j = 0; j < 4; ++j) {
                wl[j] = sWl2[lane + 32 * j][kk];
                wr[j] = sWr2[lane + 32 * j][kk];
            }
#pragma unroll
            for (int p = 0; p < 4; ++p) {
                ull a1 = *(const ull*)&sA1[kk][w * 8 + 2 * p];  // broadcast
                ull a2 = *(const ull*)&sA2[kk][w * 8 + 2 * p];
#pragma unroll
                for (int j = 0; j < 4; ++j)
                    acc[p][j] = ffma2(a1, wl[j], ffma2(a2, wr[j], acc[p][j]));
            }
        }
        __syncthreads();
    }

    float b[4];
#pragma unroll
    for (int j = 0; j < 4; ++j) b[j] = bl[lane + 32 * j];

#pragma unroll
    for (int p = 0; p < 4; ++p) {
        int n = n0 + w * 8 + 2 * p;
#pragma unroll
        for (int j = 0; j < 4; ++j) {
            float v0 = __uint_as_float((unsigned)(acc[p][j] & 0xFFFFFFFFull)) + b[j];
            float v1 = __uint_as_float((unsigned)(acc[p][j] >> 32)) + b[j];
            if (RELU) { v0 = fmaxf(v0, 0.f); v1 = fmaxf(v1, 0.f); }
            if (n < N)     out[(size_t)n * 128 + lane + 32 * j] = v0;
            if (n + 1 < N) out[(size_t)(n + 1) * 128 + lane + 32 * j] = v1;
        }
    }
}

// ---------------- launch ----------------
extern "C" void kernel_launch(void* const* d_in, const int* in_sizes, int n_in,
                              void* d_out, int out_size) {
    const float* x   = (const float*)d_in[0];
    const int*   ei  = (const int*)d_in[1];
    const float* Wl1 = (const float*)d_in[2];
    const float* bl1 = (const float*)d_in[3];
    const float* Wr1 = (const float*)d_in[4];
    const float* Wl2 = (const float*)d_in[5];
    const float* bl2 = (const float*)d_in[6];
    const float* Wr2 = (const float*)d_in[7];
    float* out = (float*)d_out;

    int N = in_sizes[0] / 64;
    int E = in_sizes[1] / 2;

    void* p;
    cudaGetSymbolAddress(&p, g_mean1); float* mean1 = (float*)p;
    cudaGetSymbolAddress(&p, g_h);     float* hbuf  = (float*)p;
    cudaGetSymbolAddress(&p, g_mean2); float* mean2 = (float*)p;

    // CSR build
    int e4 = (E + 3) / 4;
    zero_deg_kernel<<<(N + 255) / 256, 256>>>(N);
    hist_kernel<<<(e4 + 255) / 256, 256>>>(ei, E);
    scan_kernel<<<1, 1024>>>(N);
    scatter_kernel<<<(e4 + 255) / 256, 256>>>(ei, E);

    // Layer 1
    agg64_kernel<<<(N + 7) / 8, 256>>>(x, mean1, N);
    combine_kernel<64, true><<<(N + 63) / 64, 256>>>(mean1, x, Wl1, bl1, Wr1, hbuf, N);

    // Layer 2
    agg128_kernel<<<(N + 7) / 8, 256>>>(hbuf, mean2, N);
    combine_kernel<128, false><<<(N + 63) / 64, 256>>>(mean2, hbuf, Wl2, bl2, Wr2, out, N);
}